// round 6
// baseline (speedup 1.0000x reference)
#include <cuda_runtime.h>
#include <math.h>

#define BB 16
#define HH 384
#define WW 384
#define NPIX (BB * HH * WW)
#define NWORDS 12               // 384 / 32
#define TR 16                   // rows per block (output)
#define HALO 3                  // vertical halo kept in SMEM
#define NR (TR + 2 * HALO)      // 22 rows resident per block
#define NTILES (HH / TR)        // 24
#define NBLK (BB * NTILES)      // 384

// Per-block partial sums (no atomics -> fully deterministic)
__device__ float g_partial[NBLK];

// ---------------------------------------------------------------------------
// Fused kernel: one block = 16 rows x 384 cols of one image (+3-row halo).
// Phase 1: fg bitmasks for 22 rows (ballot).
// Phase 2: horizontal nearest-fg distance g (clz/ffs) -> SMEM u16. Exact;
//          no-fg row -> 768 = BIG (matches reference clip).
// Phase 3: vertical envelope min over +-HALO from SMEM, exact rare fallback
//          (direct scan of targets) if the envelope could extend past the
//          halo; fused sigmoid/|p-t|/sqrt; block reduction -> partial.
// Halo rows clamped at image edges: exact, since the clamped row is already
// included at its true (smaller) offset and r^2+g^2 can only overshoot.
// ---------------------------------------------------------------------------
__global__ void fused_kernel(const float* __restrict__ logits,
                             const int* __restrict__ targets) {
    __shared__ unsigned smask[NR][NWORDS];
    __shared__ unsigned short gsh[NR][WW];
    __shared__ float warp_sums[NWORDS];

    const int j = threadIdx.x;                  // 0..383 (column)
    const int wj = j >> 5;
    const int bj = j & 31;
    const int bid = blockIdx.x;
    const int b = bid / NTILES;
    const int row0 = (bid % NTILES) * TR;

    const int* timg = targets + (size_t)b * HH * WW;
    const float* limg = logits + (size_t)b * HH * WW;

    // Phase 1: bitmasks for NR rows (halo clamped into the image)
    #pragma unroll
    for (int rr = 0; rr < NR; ++rr) {
        const int row = min(max(row0 - HALO + rr, 0), HH - 1);
        const int fg = timg[row * WW + j] != 0;
        const unsigned m = __ballot_sync(0xFFFFFFFFu, fg);
        if (bj == 0) smask[rr][wj] = m;
    }
    __syncthreads();

    // Phase 2: horizontal distance per row via nearest set bit
    #pragma unroll 1
    for (int rr = 0; rr < NR; ++rr) {
        const unsigned* mk = smask[rr];
        const unsigned own = mk[wj];

        int dl;
        const unsigned ml = own & (0xFFFFFFFFu >> (31 - bj));
        if (ml) {
            dl = bj - (31 - __clz(ml));
        } else {
            dl = 0x7FFFFF;
            for (int w = wj - 1; w >= 0; --w) {
                const unsigned m = mk[w];
                if (m) { dl = j - (w * 32 + 31 - __clz(m)); break; }
            }
        }

        int dr;
        const unsigned mr = own & (0xFFFFFFFFu << bj);
        if (mr) {
            dr = (__ffs(mr) - 1) - bj;
        } else {
            dr = 0x7FFFFF;
            for (int w = wj + 1; w < NWORDS; ++w) {
                const unsigned m = mk[w];
                if (m) { dr = (w * 32 + __ffs(m) - 1) - j; break; }
            }
        }

        gsh[rr][j] = (unsigned short)min(min(dl, dr), 768);   // BIG = H + W
    }
    __syncthreads();

    // Phase 3: per-pixel envelope + loss for TR rows in this column
    float val = 0.0f;
    #pragma unroll 1
    for (int k = 0; k < TR; ++k) {
        const int rr = k + HALO;
        const int i = row0 + k;

        const unsigned short g0 = gsh[rr][j];
        const float f0 = (float)g0;
        float best = f0 * f0;
        #pragma unroll
        for (int r = 1; r <= HALO; ++r) {
            const float a = (float)gsh[rr - r][j];
            const float c = (float)gsh[rr + r][j];
            const float r2 = (float)(r * r);
            best = fminf(best, fmaf(a, a, r2));
            best = fminf(best, fmaf(c, c, r2));
        }

        // Exact fallback beyond the halo (P ~ 1e-8 per pixel on this data)
        if (best > (float)((HALO + 1) * (HALO + 1))) {
            #pragma unroll 1
            for (int r = HALO + 1; ; ++r) {
                const float r2 = (float)(r * r);
                if (r2 >= best) break;
                #pragma unroll 1
                for (int s = 0; s < 2; ++s) {
                    const int row = s ? min(i + r, HH - 1) : max(i - r, 0);
                    #pragma unroll 1
                    for (int dd = 0; ; ++dd) {
                        const float dd2 = (float)dd * (float)dd;
                        if (r2 + dd2 >= best) break;
                        int hit = 0;
                        if (j - dd >= 0 && timg[row * WW + j - dd]) hit = 1;
                        if (j + dd < WW && timg[row * WW + j + dd]) hit = 1;
                        if (hit) { best = r2 + dd2; break; }
                    }
                }
            }
        }

        // |sigmoid(x) - t| = 1/(1 + exp(t ? x : -x)),  t = (g0 == 0)
        const float x = limg[i * WW + j];
        const float e = __expf((g0 == 0) ? x : -x);
        val += __fdividef(sqrtf(best), 1.0f + e);
    }

    // Block reduction -> one partial per block
    #pragma unroll
    for (int off = 16; off > 0; off >>= 1)
        val += __shfl_xor_sync(0xFFFFFFFFu, val, off);
    if (bj == 0) warp_sums[wj] = val;
    __syncthreads();
    if (wj == 0) {
        float s = (bj < NWORDS) ? warp_sums[bj] : 0.0f;
        #pragma unroll
        for (int off = 8; off > 0; off >>= 1)
            s += __shfl_xor_sync(0xFFFFFFFFu, s, off);
        if (bj == 0) g_partial[bid] = s;
    }
}

// ---------------------------------------------------------------------------
// Final reduction: 384 partials -> out[0]. One block, deterministic.
// ---------------------------------------------------------------------------
__global__ void reduce_kernel(float* __restrict__ out) {
    const int t = threadIdx.x;                  // 0..383
    float v = g_partial[t];
    #pragma unroll
    for (int off = 16; off > 0; off >>= 1)
        v += __shfl_xor_sync(0xFFFFFFFFu, v, off);

    __shared__ float ws[NWORDS];
    if ((t & 31) == 0) ws[t >> 5] = v;
    __syncthreads();
    if (t < 32) {
        float s = (t < NWORDS) ? ws[t] : 0.0f;
        #pragma unroll
        for (int off = 8; off > 0; off >>= 1)
            s += __shfl_xor_sync(0xFFFFFFFFu, s, off);
        if (t == 0) out[0] = s * (1.0f / (float)NPIX);
    }
}

extern "C" void kernel_launch(void* const* d_in, const int* in_sizes, int n_in,
                              void* d_out, int out_size) {
    const float* logits = (const float*)d_in[0];
    const int* targets = (const int*)d_in[1];
    float* out = (float*)d_out;

    (void)in_sizes; (void)n_in; (void)out_size;

    fused_kernel<<<NBLK, WW>>>(logits, targets);
    reduce_kernel<<<1, WW>>>(out);
}

// round 7
// speedup vs baseline: 1.6600x; 1.6600x over previous
#include <cuda_runtime.h>
#include <math.h>

#define BB 16
#define HH 384
#define WW 384
#define NPIX (BB * HH * WW)
#define TILE 8                  // output rows per block
#define NRR (TILE + 6)          // mask rows incl +-3 halo = 14
#define WPR 14                  // words per mask row: 1 pad + 12 + 1 pad
#define NTILES (HH / TILE)      // 48
#define NBLK (BB * NTILES)      // 768
#define TABBIG 589824           // 768^2 = clipped-BIG^2 (matches reference)

__device__ float g_partial[NBLK];
__device__ int g_count = 0;     // reset by finisher each run

// ---------------------------------------------------------------------------
// Exact pruned brute-force EDT fallback (P ~ 2^-45 per pixel on this data).
// ub is a valid upper bound (window candidates are genuine distances; clamped
// halo rows only overshoot). Returns exact min(ub, true d^2), reproducing the
// reference's BIG-clip when no foreground exists.
// ---------------------------------------------------------------------------
__device__ __noinline__ int edt_fallback(const int* __restrict__ timg,
                                         int i, int j, int ub) {
    int best = ub;
    for (int r = 0; r < HH; ++r) {
        if (r * r >= best) break;
        #pragma unroll 1
        for (int s = 0; s < 2; ++s) {
            if (s == 1 && r == 0) continue;
            const int row = s ? i + r : i - r;
            if (row < 0 || row >= HH) continue;
            for (int dd = 0; ; ++dd) {
                const int d2 = r * r + dd * dd;
                if (d2 >= best) break;
                int hit = 0;
                if (j - dd >= 0 && timg[row * WW + j - dd]) hit = 1;
                if (j + dd < WW && timg[row * WW + j + dd]) hit = 1;
                if (hit) { best = d2; break; }
            }
        }
    }
    return best;
}

// ---------------------------------------------------------------------------
// Fused single-pass kernel. Block = 8 rows x 384 cols of one image.
// Phase A: fg bitmasks for 14 rows (ballot), zero-padded words at both ends;
//          halo rows clamped at image edges (exact: clamped row already
//          counted at its true smaller offset, r^2+g^2 only overshoots).
// Phase B: per pixel, 32-bit window per row via funnelshift; fold +-r rows by
//          OR; 4 smem-table lookups give min dd^2; best = min_k(k^2 + tab).
//          best < 16 is provably exact; else exact fallback. Fused with
//          sigmoid loss (|sig(x)-t| = 1/(1+exp(t?x:-x)), t = center bit).
// Tail: block reduction -> partial; last finished block sums all partials
//       in a fixed deterministic tree and writes out[0].
// ---------------------------------------------------------------------------
__global__ __launch_bounds__(WW)
void fused_kernel(const float* __restrict__ logits,
                  const int* __restrict__ targets,
                  float* __restrict__ out) {
    __shared__ unsigned pm[NRR][WPR];
    __shared__ int tabs[128];
    __shared__ float sqtab[32];
    __shared__ float warp_sums[WW / 32];
    __shared__ int is_last;

    const int tid = threadIdx.x;                // 0..383
    const int bid = blockIdx.x;
    const int b = bid / NTILES;
    const int row0 = (bid % NTILES) * TILE;

    const int* timg = targets + (size_t)b * HH * WW;
    const float* limg = logits + (size_t)b * HH * WW;

    // Tables + pad words
    if (tid < 128) {
        const unsigned w = (unsigned)tid;
        tabs[tid] = (w & 0x08u) ? 0 :
                    (w & 0x14u) ? 1 :
                    (w & 0x22u) ? 4 :
                    (w & 0x41u) ? 9 : TABBIG;
        if (tid < 32) sqtab[tid] = sqrtf((float)tid);
        if (tid < NRR) { pm[tid][0] = 0u; pm[tid][WPR - 1] = 0u; }
    }

    // Phase A: bitmasks (rows clamped into image)
    const int lane = tid & 31;
    #pragma unroll
    for (int rr = 0; rr < NRR; ++rr) {
        const int row = min(max(row0 - 3 + rr, 0), HH - 1);
        const int fg = timg[row * WW + tid] != 0;
        const unsigned m = __ballot_sync(0xFFFFFFFFu, fg);
        if (lane == 0) pm[rr][1 + (tid >> 5)] = m;
    }
    __syncthreads();

    // Phase B: thread -> column quad q (4 cols) x 2 adjacent rows
    const int q = tid % 96;
    const int kl = (tid / 96) * 2;              // 0,2,4,6
    const int j = q * 4;
    const int word = (j + 29) >> 5;             // bitpos of col j-3, padded
    const int sh = (j + 29) & 31;

    unsigned win[8];                            // mask rows kl .. kl+7
    #pragma unroll
    for (int w = 0; w < 8; ++w) {
        const unsigned* rp = pm[kl + w];
        win[w] = __funnelshift_r(rp[word], rp[word + 1], sh);
    }

    float val = 0.0f;
    #pragma unroll
    for (int m = 0; m < 2; ++m) {
        const int ci = 3 + m;                   // center within win[]
        const int i = row0 + kl + m;
        const unsigned A0 = win[ci];
        const unsigned A1 = win[ci - 1] | win[ci + 1];
        const unsigned A2 = win[ci - 2] | win[ci + 2];
        const unsigned A3 = win[ci - 3] | win[ci + 3];

        const float4 lg = *(const float4*)(limg + i * WW + j);
        const float xs[4] = {lg.x, lg.y, lg.z, lg.w};

        #pragma unroll
        for (int c = 0; c < 4; ++c) {
            const int b0 = tabs[(A0 >> c) & 127u];
            const int b1 = tabs[(A1 >> c) & 127u] + 1;
            const int b2 = tabs[(A2 >> c) & 127u] + 4;
            const int b3 = tabs[(A3 >> c) & 127u] + 9;
            int best = min(min(b0, b1), min(b2, b3));
            if (best >= 16) best = edt_fallback(timg, i, j + c, best);

            const int tbit = (A0 >> (c + 3)) & 1u;
            const float e = __expf(tbit ? xs[c] : -xs[c]);
            const float sq = (best < 32) ? sqtab[best] : sqrtf((float)best);
            val += __fdividef(sq, 1.0f + e);
        }
    }

    // Block reduction
    #pragma unroll
    for (int off = 16; off > 0; off >>= 1)
        val += __shfl_xor_sync(0xFFFFFFFFu, val, off);
    if (lane == 0) warp_sums[tid >> 5] = val;
    __syncthreads();
    if (tid < 32) {
        float s = (tid < WW / 32) ? warp_sums[tid] : 0.0f;
        #pragma unroll
        for (int off = 16; off > 0; off >>= 1)
            s += __shfl_xor_sync(0xFFFFFFFFu, s, off);
        if (tid == 0) {
            g_partial[bid] = s;
            __threadfence();
            const int done = atomicAdd(&g_count, 1);
            is_last = (done == NBLK - 1);
        }
    }
    __syncthreads();

    // Last block: deterministic final sum of all 768 partials
    if (is_last) {
        __threadfence();
        float v = g_partial[tid] + g_partial[tid + WW];
        #pragma unroll
        for (int off = 16; off > 0; off >>= 1)
            v += __shfl_xor_sync(0xFFFFFFFFu, v, off);
        if (lane == 0) warp_sums[tid >> 5] = v;
        __syncthreads();
        if (tid < 32) {
            float s = (tid < WW / 32) ? warp_sums[tid] : 0.0f;
            #pragma unroll
            for (int off = 16; off > 0; off >>= 1)
                s += __shfl_xor_sync(0xFFFFFFFFu, s, off);
            if (tid == 0) {
                out[0] = s * (1.0f / (float)NPIX);
                g_count = 0;                    // reset for next graph replay
            }
        }
    }
}

extern "C" void kernel_launch(void* const* d_in, const int* in_sizes, int n_in,
                              void* d_out, int out_size) {
    const float* logits = (const float*)d_in[0];
    const int* targets = (const int*)d_in[1];
    float* out = (float*)d_out;

    (void)in_sizes; (void)n_in; (void)out_size;

    fused_kernel<<<NBLK, WW>>>(logits, targets, out);
}